// round 2
// baseline (speedup 1.0000x reference)
#include <cuda_runtime.h>

// Problem constants (fixed by the reference)
#define N_ROWS   2000000
#define D        128
#define C        1000
#define DECAY    0.3f

// Phase-1 tiling: 4 column slices of 32, 37 row chunks -> 148 CTAs (one wave)
#define SLICES      4
#define SLICE_D     32
#define ROW_CHUNKS  37
#define P1_THREADS  1024
#define P1_WARPS    (P1_THREADS / 32)

// Global scratch (allocation-free: __device__ arrays)
__device__ float g_sums[C * D];     // 512 KB
__device__ float g_counts[C];
__device__ int   g_present[C];

// ---------------------------------------------------------------------------
// Zero the scratch (must run every launch; buffers persist across graph replays)
// ---------------------------------------------------------------------------
__global__ void zero_kernel() {
    int tid    = blockIdx.x * blockDim.x + threadIdx.x;
    int stride = gridDim.x * blockDim.x;
    for (int i = tid; i < C * D; i += stride) g_sums[i] = 0.0f;
    if (tid < C) { g_counts[tid] = 0.0f; g_present[tid] = 0; }
}

// ---------------------------------------------------------------------------
// Counts + presence histogram (smem-privatized, then global atomics)
// mask is int32 (bool promoted by the harness).
// ---------------------------------------------------------------------------
__global__ void counts_kernel(const int* __restrict__ y,
                              const int* __restrict__ mask) {
    __shared__ float s_cnt[C];
    __shared__ int   s_pres[C];
    for (int i = threadIdx.x; i < C; i += blockDim.x) { s_cnt[i] = 0.0f; s_pres[i] = 0; }
    __syncthreads();

    int stride = gridDim.x * blockDim.x;
    for (int i = blockIdx.x * blockDim.x + threadIdx.x; i < N_ROWS; i += stride) {
        int cls = y[i];
        atomicAdd(&s_pres[cls], 1);                   // presence: unmasked (torch.unique(y))
        if (mask[i]) atomicAdd(&s_cnt[cls], 1.0f);    // count: masked
    }
    __syncthreads();

    for (int i = threadIdx.x; i < C; i += blockDim.x) {
        if (s_pres[i])        atomicAdd(&g_present[i], s_pres[i]);
        if (s_cnt[i] != 0.0f) atomicAdd(&g_counts[i],  s_cnt[i]);
    }
}

// ---------------------------------------------------------------------------
// Phase 1: per-(row-chunk, column-slice) smem-privatized segment sum.
// One warp per row step: lane d loads x[row, slice*32 + d] (128B coalesced),
// then a spread-address smem atomicAdd into s_acc[class][d].
// ---------------------------------------------------------------------------
__global__ void __launch_bounds__(P1_THREADS, 1)
accum_kernel(const float* __restrict__ x,
             const int* __restrict__ y,
             const int* __restrict__ mask) {
    extern __shared__ float s_acc[];  // [C * SLICE_D] = 125 KB

    const int slice = blockIdx.x;
    const int chunk = blockIdx.y;

    for (int i = threadIdx.x; i < C * SLICE_D; i += P1_THREADS) s_acc[i] = 0.0f;
    __syncthreads();

    const int warp = threadIdx.x >> 5;
    const int lane = threadIdx.x & 31;
    const int col  = slice * SLICE_D + lane;

    const int rpc  = (N_ROWS + ROW_CHUNKS - 1) / ROW_CHUNKS;
    const int row0 = chunk * rpc;
    const int row1 = (row0 + rpc < N_ROWS) ? (row0 + rpc) : N_ROWS;

    int r = row0 + warp;
    // 4x row unroll for MLP (4 outstanding 128B loads per warp)
    for (; r + 3 * P1_WARPS < row1; r += 4 * P1_WARPS) {
        const int ra = r, rb = r + P1_WARPS, rc = r + 2 * P1_WARPS, rd = r + 3 * P1_WARPS;
        const int c0 = y[ra], c1 = y[rb], c2 = y[rc], c3 = y[rd];
        const int m0 = mask[ra], m1 = mask[rb], m2 = mask[rc], m3 = mask[rd];
        const float v0 = x[(long)ra * D + col];
        const float v1 = x[(long)rb * D + col];
        const float v2 = x[(long)rc * D + col];
        const float v3 = x[(long)rd * D + col];
        if (m0) atomicAdd(&s_acc[c0 * SLICE_D + lane], v0);
        if (m1) atomicAdd(&s_acc[c1 * SLICE_D + lane], v1);
        if (m2) atomicAdd(&s_acc[c2 * SLICE_D + lane], v2);
        if (m3) atomicAdd(&s_acc[c3 * SLICE_D + lane], v3);
    }
    for (; r < row1; r += P1_WARPS) {
        const int cls = y[r];
        if (mask[r]) atomicAdd(&s_acc[cls * SLICE_D + lane], x[(long)r * D + col]);
    }
    __syncthreads();

    // Flush slice into global sums (37 adders per address -> mild contention)
    for (int i = threadIdx.x; i < C * SLICE_D; i += P1_THREADS) {
        const float v = s_acc[i];
        if (v != 0.0f) {
            const int c = i / SLICE_D;
            const int l = i - c * SLICE_D;
            atomicAdd(&g_sums[c * D + slice * SLICE_D + l], v);
        }
    }
}

// ---------------------------------------------------------------------------
// Finalize: avg = sums / max(counts,1); ema; select by presence
// ---------------------------------------------------------------------------
__global__ void finalize_kernel(const float* __restrict__ centroids,
                                float* __restrict__ out) {
    const int c = blockIdx.x;
    const int d = threadIdx.x;
    const float cent = centroids[c * D + d];
    float o = cent;
    if (g_present[c] > 0) {
        const float avg = g_sums[c * D + d] / fmaxf(g_counts[c], 1.0f);
        o = DECAY * avg + (1.0f - DECAY) * cent;
    }
    out[c * D + d] = o;
}

// ---------------------------------------------------------------------------
// Launch
// ---------------------------------------------------------------------------
extern "C" void kernel_launch(void* const* d_in, const int* in_sizes, int n_in,
                              void* d_out, int out_size) {
    const float* x         = (const float*)d_in[0];
    const int*   y         = (const int*)d_in[1];
    const int*   mask      = (const int*)d_in[2];
    const float* centroids = (const float*)d_in[3];
    float*       out       = (float*)d_out;

    (void)in_sizes; (void)n_in; (void)out_size;

    cudaFuncSetAttribute(accum_kernel,
                         cudaFuncAttributeMaxDynamicSharedMemorySize,
                         C * SLICE_D * (int)sizeof(float));

    zero_kernel<<<128, 256>>>();
    counts_kernel<<<148, 256>>>(y, mask);
    accum_kernel<<<dim3(SLICES, ROW_CHUNKS), P1_THREADS,
                   C * SLICE_D * sizeof(float)>>>(x, y, mask);
    finalize_kernel<<<C, D>>>(centroids, out);
}